// round 2
// baseline (speedup 1.0000x reference)
#include <cuda_runtime.h>
#include <math.h>

#define BB   32
#define LL   4096
#define DIN  32
#define HH   256
#define NN   32
#define DOUT 16
#define J1   128   // H/2

// Scratch (device globals: allocation-free per harness rules)
__device__ float g_hrelu[BB*LL*J1];   // 64 MB: relu(data@w1+b1), row-major (b*L+m, j)
__device__ float g_kt[LL*HH];         // 4 MB: kt[m][h] = k[h][L-1-m] (+D[h] at m=L-1)
__device__ float g_part[BB*64*HH];    // 2 MB: partial sums per (b, m-block, h)

// ---------------- kernel 1: hrelu = relu(data @ w1 + b1) ----------------
__global__ void __launch_bounds__(256) k_hrelu(const float* __restrict__ data,
                                               const float* __restrict__ w1,
                                               const float* __restrict__ b1) {
    __shared__ float sd[16][DIN];
    __shared__ float sw[DIN*J1];
    int tid = threadIdx.x;
    int row0 = blockIdx.x * 16;
    for (int u = tid; u < DIN*J1; u += 256) sw[u] = w1[u];
    for (int u = tid; u < 16*DIN; u += 256) {
        int r = u >> 5, i = u & 31;
        sd[r][i] = data[(size_t)(row0 + r)*DIN + i];
    }
    __syncthreads();
    int j  = tid & 127;
    int rr = tid >> 7;
    float bj = b1[j];
    #pragma unroll
    for (int r = rr; r < 16; r += 2) {
        float s = bj;
        #pragma unroll
        for (int i = 0; i < DIN; i++) s += sd[r][i] * sw[i*J1 + j];
        g_hrelu[(size_t)(row0 + r)*J1 + j] = fmaxf(s, 0.f);
    }
}

// ---------------- kernel 2: SSM kernel k, stored reversed+transposed ----------------
// k[h,l] = 2*Re( sum_n C[h,n]*(exp(dtA)-1)/A * exp(dtA*l) )
// Thread = h (256/block), block = l-chunk of 32. Complex-power recurrence per n,
// chunk start phase reduced mod 2*pi in double for accuracy.
__global__ void __launch_bounds__(256) k_kt(const float* __restrict__ log_dt,
                                            const float* __restrict__ A_re,
                                            const float* __restrict__ A_im,
                                            const float* __restrict__ C_re,
                                            const float* __restrict__ C_im,
                                            const float* __restrict__ Dv) {
    const int h  = threadIdx.x;
    const int l0 = blockIdx.x * 32;
    float acc[32];
    #pragma unroll
    for (int i = 0; i < 32; i++) acc[i] = 0.f;
    float dt = expf(log_dt[h]);
    for (int n = 0; n < NN; n++) {
        float are = A_re[h*NN+n], aim = A_im[h*NN+n];
        float dre = dt*are, dim = dt*aim;
        float er = expf(dre);
        float ws, wc; sincosf(dim, &ws, &wc);
        float wre = er*wc, wim = er*ws;                 // w = exp(dtA)
        float nre = wre - 1.f, nim = wim;               // exp(dtA)-1
        float inv = 1.f/(are*are + aim*aim);
        float qre = (nre*are + nim*aim)*inv;            // (w-1)/A
        float qim = (nim*are - nre*aim)*inv;
        float cre = C_re[h*NN+n], cim = C_im[h*NN+n];
        float kre = cre*qre - cim*qim;                  // Kcoef
        float kim = cre*qim + cim*qre;
        // p = exp(dtA * l0): magnitude in float, phase range-reduced in double
        const double TWO_PI = 6.283185307179586476925286766559;
        double th = (double)dim * (double)l0;
        float thr = (float)(th - TWO_PI * rint(th * (1.0/TWO_PI)));
        float mag = expf(dre * (float)l0);
        float ps, pc; sincosf(thr, &ps, &pc);
        float pre = mag*pc, pim = mag*ps;
        #pragma unroll
        for (int i = 0; i < 32; i++) {
            acc[i] += kre*pre - kim*pim;                // Re(Kc * p)
            float t = pre*wre - pim*wim;                // p *= w
            pim = pre*wim + pim*wre;
            pre = t;
        }
    }
    float dh = Dv[h];
    #pragma unroll
    for (int i = 0; i < 32; i++) {
        int l = l0 + i;
        float v = 2.f*acc[i];
        if (l == 0) v += dh;                            // D folded at m = L-1
        g_kt[(size_t)(LL-1-l)*HH + h] = v;              // reversed + transposed
    }
}

// ---------------- kernel 3: fused x = hrelu@w2+b2, then y_part = sum_m x*kt --------
// 64(m) x 64(h) tile per block, 256 threads, 4x4 register tile (strided mapping).
__global__ void __launch_bounds__(256) k_gemm(const float* __restrict__ w2,
                                              const float* __restrict__ b2) {
    __shared__ float As[32][65];
    __shared__ float Ws[32][64];
    __shared__ float red[64*17];
    int tid = threadIdx.x;
    int tx = tid & 15, ty = tid >> 4;
    int row0 = blockIdx.x * 64;
    int h0   = blockIdx.y * 64;
    float acc[4][4];
    #pragma unroll
    for (int i = 0; i < 4; i++)
        #pragma unroll
        for (int j = 0; j < 4; j++) acc[i][j] = 0.f;

    for (int k0 = 0; k0 < J1; k0 += 32) {
        #pragma unroll
        for (int u = 0; u < 8; u++) {
            int idx = tid + u*256;
            int k = idx & 31, r = idx >> 5;
            As[k][r] = g_hrelu[(size_t)(row0 + r)*J1 + k0 + k];
        }
        #pragma unroll
        for (int u = 0; u < 8; u++) {
            int idx = tid + u*256;
            int hh = idx & 63, kk = idx >> 6;
            Ws[kk][hh] = w2[(size_t)(k0+kk)*HH + h0 + hh];
        }
        __syncthreads();
        #pragma unroll
        for (int kk = 0; kk < 32; kk++) {
            float a[4], w[4];
            #pragma unroll
            for (int i = 0; i < 4; i++) a[i] = As[kk][ty + i*16];
            #pragma unroll
            for (int j = 0; j < 4; j++) w[j] = Ws[kk][tx + j*16];
            #pragma unroll
            for (int i = 0; i < 4; i++)
                #pragma unroll
                for (int j = 0; j < 4; j++) acc[i][j] += a[i]*w[j];
        }
        __syncthreads();
    }
    // epilogue: x = acc + b2; multiply by kt; reduce m within block
    int b     = row0 >> 12;     // row0 / 4096 (blocks never straddle b)
    int mloc0 = row0 & 4095;
    float part[4] = {0.f, 0.f, 0.f, 0.f};
    #pragma unroll
    for (int j = 0; j < 4; j++) {
        int hcol = h0 + tx + j*16;
        float b2v = b2[hcol];
        #pragma unroll
        for (int i = 0; i < 4; i++) {
            int m = mloc0 + ty + i*16;
            float x = acc[i][j] + b2v;
            part[j] += x * g_kt[(size_t)m*HH + hcol];
        }
    }
    #pragma unroll
    for (int j = 0; j < 4; j++) red[(tx + j*16)*17 + ty] = part[j];
    __syncthreads();
    if (tid < 64) {
        float s = 0.f;
        #pragma unroll
        for (int q = 0; q < 16; q++) s += red[tid*17 + q];
        int mblk = blockIdx.x & 63;
        g_part[(size_t)(b*64 + mblk)*HH + h0 + tid] = s;
    }
}

// ---------------- kernel 4: reduce partials + full head (gelu/Wg/GLU/w3/w4) --------
__global__ void __launch_bounds__(256) k_head(const float* __restrict__ Wg,
                                              const float* __restrict__ bg,
                                              const float* __restrict__ w3,
                                              const float* __restrict__ b3,
                                              const float* __restrict__ w4,
                                              const float* __restrict__ b4,
                                              float* __restrict__ out) {
    int b = blockIdx.x, t = threadIdx.x;
    __shared__ float gsh[HH];
    __shared__ float glu[HH];
    __shared__ float zsh[J1];
    float y = 0.f;
    #pragma unroll 4
    for (int mb = 0; mb < 64; mb++) y += g_part[(size_t)(b*64 + mb)*HH + t];
    // exact gelu: x * 0.5 * (1 + erf(x/sqrt(2)))
    float g = 0.5f * y * (1.f + erff(y * 0.70710678118654752f));
    gsh[t] = g;
    __syncthreads();
    float a  = bg[t];
    float bs = bg[HH + t];
    #pragma unroll 4
    for (int h = 0; h < HH; h++) {
        float gv = gsh[h];
        a  += gv * Wg[(size_t)h*(2*HH) + t];
        bs += gv * Wg[(size_t)h*(2*HH) + HH + t];
    }
    glu[t] = a / (1.f + expf(-bs));
    __syncthreads();
    if (t < J1) {
        float z = b3[t];
        #pragma unroll 4
        for (int h = 0; h < HH; h++) z += glu[h] * w3[(size_t)h*J1 + t];
        zsh[t] = fmaxf(z, 0.f);
    }
    __syncthreads();
    if (t < DOUT) {
        float o = b4[t];
        #pragma unroll 4
        for (int j = 0; j < J1; j++) o += zsh[j] * w4[j*DOUT + t];
        out[b*DOUT + t] = o;
    }
}

extern "C" void kernel_launch(void* const* d_in, const int* in_sizes, int n_in,
                              void* d_out, int out_size) {
    const float* data   = (const float*)d_in[0];
    const float* w1     = (const float*)d_in[1];
    const float* b1     = (const float*)d_in[2];
    const float* w2     = (const float*)d_in[3];
    const float* b2     = (const float*)d_in[4];
    const float* log_dt = (const float*)d_in[5];
    const float* A_re   = (const float*)d_in[6];
    const float* A_im   = (const float*)d_in[7];
    const float* C_re   = (const float*)d_in[8];
    const float* C_im   = (const float*)d_in[9];
    const float* Dv     = (const float*)d_in[10];
    const float* Wg     = (const float*)d_in[11];
    const float* bg     = (const float*)d_in[12];
    const float* w3     = (const float*)d_in[13];
    const float* b3     = (const float*)d_in[14];
    const float* w4     = (const float*)d_in[15];
    const float* b4     = (const float*)d_in[16];
    float* out = (float*)d_out;

    k_kt<<<LL/32, 256>>>(log_dt, A_re, A_im, C_re, C_im, Dv);
    k_hrelu<<<BB*LL/16, 256>>>(data, w1, b1);
    dim3 g3(BB*LL/64, HH/64);
    k_gemm<<<g3, 256>>>(w2, b2);
    k_head<<<BB, 256>>>(Wg, bg, w3, b3, w4, b4, out);
}